// round 16
// baseline (speedup 1.0000x reference)
#include <cuda_runtime.h>
#include <cuda_bf16.h>
#include <cuda_fp16.h>
#include <math.h>
#include <stdint.h>

#define NP   8192
#define DIN_ 1024
#define DH_  256
#define CANDS 384
#define NEG_INF (-3.402823466e38f)

// ---------------- scratch (allocation-free: __device__ globals) ----------------
__device__ float g_x [NP*DH_];
__device__ float g_eh[NP*DH_];
__device__ float g_et[NP*DH_];
__device__ __nv_bfloat16 g_Ps [(size_t)NP*2048];    // x_path split [h|l]
__device__ __nv_bfloat16 g_Xs [(size_t)NP*512];     // mixed x split [h|l]
__device__ __half g_Ah [(size_t)NP*DH_];            // e_h fp16 (NT A)
__device__ __half g_Bh [(size_t)NP*DH_];            // e_t fp16 (NT B)
__device__ __nv_bfloat16 g_As [(size_t)NP*512];     // a split [h|l]
__device__ __nv_bfloat16 g_Ms [(size_t)NP*512];     // m split [h|l]
__device__ __nv_bfloat16 g_Es [(size_t)NP*512];     // e_msg split [h|l]
__device__ __nv_bfloat16 g_Wfc1s[(size_t)DH_*2048]; // fc1 W [h|l]
__device__ __nv_bfloat16 g_Wcat [512*512];          // [Wh;Wt] [h|l]
__device__ __nv_bfloat16 g_W1s [DH_*512];
__device__ __nv_bfloat16 g_W2s [DH_*512];
__device__ __nv_bfloat16 g_Ag1s[(DH_/2)*512];
__device__ float g_bcat[512];
__device__ float g_candv[(size_t)NP*CANDS];
__device__ int   g_candi[(size_t)NP*CANDS];
__device__ float g_h [NP*(DH_/2)];
__device__ float g_mean[DH_];
__device__ float g_s[NP];
__device__ float g_stat[2];

__device__ __forceinline__ float leaky_f(float v) { return v > 0.f ? v : 0.01f * v; }

__device__ __forceinline__ float warp_sum(float v) {
    #pragma unroll
    for (int o = 16; o > 0; o >>= 1) v += __shfl_down_sync(0xffffffffu, v, o);
    return v;
}

// ---------------- PTX helpers ----------------
__device__ __forceinline__ uint32_t smem_u32(const void* p) {
    uint32_t a;
    asm("{ .reg .u64 t; cvta.to.shared.u64 t, %1; cvt.u32.u64 %0, t; }" : "=r"(a) : "l"(p));
    return a;
}
__device__ __forceinline__ void cp16(uint32_t dst, const void* src) {
    asm volatile("cp.async.cg.shared.global [%0], [%1], 16;" :: "r"(dst), "l"(src));
}
#define CP_COMMIT()  asm volatile("cp.async.commit_group;" ::: "memory")
#define CP_WAIT1()   asm volatile("cp.async.wait_group 1;" ::: "memory")
#define CP_WAIT0()   asm volatile("cp.async.wait_group 0;" ::: "memory")

__device__ __forceinline__ void ldsm_x4(uint32_t (&r)[4], uint32_t addr) {
    asm volatile("ldmatrix.sync.aligned.m8n8.x4.shared.b16 {%0,%1,%2,%3}, [%4];"
                 : "=r"(r[0]), "=r"(r[1]), "=r"(r[2]), "=r"(r[3]) : "r"(addr));
}
__device__ __forceinline__ void mma_bf16(float (&d)[4], const uint32_t (&a)[4],
                                         const uint32_t* b) {
    asm volatile("mma.sync.aligned.m16n8k16.row.col.f32.bf16.bf16.f32 "
                 "{%0,%1,%2,%3}, {%4,%5,%6,%7}, {%8,%9}, {%0,%1,%2,%3};"
                 : "+f"(d[0]), "+f"(d[1]), "+f"(d[2]), "+f"(d[3])
                 : "r"(a[0]), "r"(a[1]), "r"(a[2]), "r"(a[3]), "r"(b[0]), "r"(b[1]));
}
__device__ __forceinline__ void mma_f16acc(uint32_t (&d)[2], const uint32_t (&a)[4],
                                           const uint32_t* b) {
    asm volatile("mma.sync.aligned.m16n8k16.row.col.f16.f16.f16.f16 "
                 "{%0,%1}, {%2,%3,%4,%5}, {%6,%7}, {%0,%1};"
                 : "+r"(d[0]), "+r"(d[1])
                 : "r"(a[0]), "r"(a[1]), "r"(a[2]), "r"(a[3]), "r"(b[0]), "r"(b[1]));
}

__device__ __forceinline__ void split_pair(float v0, float v1,
                                           __nv_bfloat162& hh, __nv_bfloat162& ll) {
    __nv_bfloat16 h0 = __float2bfloat16(v0), h1 = __float2bfloat16(v1);
    hh.x = h0; hh.y = h1;
    ll.x = __float2bfloat16(v0 - __bfloat162float(h0));
    ll.y = __float2bfloat16(v1 - __bfloat162float(h1));
}

// ---------------- prep 1: weight splits [h|l] ----------------
__device__ __forceinline__ void splitw_body(const float* __restrict__ W,
                                            __nv_bfloat16* __restrict__ out,
                                            int K, int N, int baseRow, int idx) {
    int k = idx / N, n = idx - k * N;
    float v = W[idx];
    __nv_bfloat16 h = __float2bfloat16(v);
    __nv_bfloat16 l = __float2bfloat16(v - __bfloat162float(h));
    size_t o = (size_t)(n + baseRow) * (2 * K);
    out[o + k]     = h;
    out[o + K + k] = l;
}

__global__ void prep_w_kernel(const float* __restrict__ fc1W,
                              const float* __restrict__ Wh, const float* __restrict__ Wt,
                              const float* __restrict__ W1, const float* __restrict__ W2,
                              const float* __restrict__ Ag1) {
    int b = blockIdx.x, t = threadIdx.x;
    if (b < 1024)       splitw_body(fc1W, g_Wfc1s, DIN_, DH_, 0,   b * 256 + t);
    else if (b < 1280)  splitw_body(Wh,   g_Wcat,  DH_, DH_, 0,   (b - 1024) * 256 + t);
    else if (b < 1536)  splitw_body(Wt,   g_Wcat,  DH_, DH_, 256, (b - 1280) * 256 + t);
    else if (b < 1792)  splitw_body(W1,   g_W1s,   DH_, DH_, 0,   (b - 1536) * 256 + t);
    else if (b < 2048)  splitw_body(W2,   g_W2s,   DH_, DH_, 0,   (b - 1792) * 256 + t);
    else                splitw_body(Ag1,  g_Ag1s,  DH_, DH_/2, 0, (b - 2048) * 256 + t);
}

// ---------------- prep 2: zero g_x (for fc1 K-split atomics) + g_s + bcat --------------
__global__ void prep_z_kernel(const float* __restrict__ bh, const float* __restrict__ bt,
                              float* __restrict__ eg) {
    int b = blockIdx.x, t = threadIdx.x;
    if (b < 2048) {
        ((float4*)g_x)[b * 256 + t] = make_float4(0.f, 0.f, 0.f, 0.f);
        return;
    }
    int b2 = b - 2048;
    if (b2 < 32) { g_s[b2 * 256 + t] = 0.f; return; }
    g_mean[t] = 0.f;
    eg[t] = 0.f;
    g_bcat[t] = bh[t];
    g_bcat[256 + t] = bt[t];
}

// ---------------- A split: x_path (M x 1024 fp32) -> (M x 2048 bf16) [h|l] ----------------
__global__ __launch_bounds__(256)
void splita_kernel(const float* __restrict__ A, __nv_bfloat16* __restrict__ out, int K) {
    int idx = blockIdx.x * 256 + threadIdx.x;
    int half = K >> 1;
    int row = idx / half, c2 = idx - row * half;
    int col = c2 * 2;
    float2 v = *(const float2*)(A + (size_t)row * K + col);
    __nv_bfloat162 hh, ll;
    split_pair(v.x, v.y, hh, ll);
    size_t o = (size_t)row * (2 * K) + col;
    *(__nv_bfloat162*)&out[o]     = hh;
    *(__nv_bfloat162*)&out[o + K] = ll;
}

// ---------------- fc1 post: bias + leaky + colsum (after K-split accumulation) ---------
__global__ __launch_bounds__(256)
void fc1_post_kernel(const float* __restrict__ bias) {
    int t = threadIdx.x;                 // column
    int r0 = blockIdx.x * 256;           // 32 blocks x 256 rows
    float b = bias[t];
    float acc = 0.f;
    for (int r = 0; r < 256; r++) {
        size_t idx = (size_t)(r0 + r) * DH_ + t;
        float v = leaky_f(g_x[idx] + b);
        g_x[idx] = v;
        acc += v;
    }
    atomicAdd(&g_mean[t], acc);
}

// ---------------- mean mix (+fused [h|l] split of x) ----------------
__global__ __launch_bounds__(256)
void mix_split_kernel() {
    int idx = blockIdx.x * 256 + threadIdx.x;
    int row = idx >> 7, c2 = idx & 127;
    int col = c2 * 2;
    float2 v = *(const float2*)(g_x + (size_t)row * DH_ + col);
    float x0 = (v.x + g_mean[col]     * (1.f / (float)NP)) * 0.5f;
    float x1 = (v.y + g_mean[col + 1] * (1.f / (float)NP)) * 0.5f;
    __nv_bfloat162 hh, ll;
    split_pair(x0, x1, hh, ll);
    size_t o = (size_t)row * 512 + col;
    *(__nv_bfloat162*)&g_Xs[o]       = hh;
    *(__nv_bfloat162*)&g_Xs[o + 256] = ll;
}

// ---------------- combine: out = g_eh + g_et (leaky already applied), emit Es ----------
__global__ __launch_bounds__(256)
void combine_kernel(float* __restrict__ out) {
    int idx = blockIdx.x * 256 + threadIdx.x;
    int row = idx >> 7, c2 = idx & 127;
    int col = c2 * 2;
    size_t o = (size_t)row * DH_ + col;
    float2 a = *(const float2*)(g_eh + o);
    float2 b = *(const float2*)(g_et + o);
    float v0 = a.x + b.x, v1 = a.y + b.y;
    float2 w; w.x = v0; w.y = v1;
    *(float2*)(out + o) = w;
    __nv_bfloat162 hh, ll;
    split_pair(v0, v1, hh, ll);
    size_t so = (size_t)row * 512 + col;
    *(__nv_bfloat162*)&g_Es[so]       = hh;
    *(__nv_bfloat162*)&g_Es[so + 256] = ll;
}

// ---------------- generic mma.sync linear (BM=64, BN=128, BK=64, 2-stage, occ 3) -------
// SPLIT: 0 none, 3 ehet routing, 4 fused score, 5 raw fp32 atomic out (fc1 K-split,
//        blockIdx.z = K-half), 6 dual operand set (blockIdx.z selects A2/B2/bias2/C2).
#define L_AST   9216                     // 64*144
#define L_STAGE 27648                    // + 128*144
#define LSMEM_DYN (2 * L_STAGE + 512)

template<bool LEAKY, bool ADD, int SPLIT, bool COLSUM, int KMAP>
__global__ __launch_bounds__(256, 3)
void lin_mma(const __nv_bfloat16* A, const __nv_bfloat16* Bw,
             const float* bias, const float* Cin,
             float* C, __nv_bfloat16* S, const float* aux,
             const __nv_bfloat16* A2, const __nv_bfloat16* B2,
             const float* bias2, float* C2, int N)
{
    extern __shared__ char smem[];
    const int tid = threadIdx.x;
    const int lane = tid & 31, wid = tid >> 5;
    const int wr = wid >> 2, wc = wid & 3;
    const int bx = blockIdx.x, by = blockIdx.y;
    if (SPLIT == 6 && blockIdx.z == 1) { A = A2; Bw = B2; bias = bias2; C = C2; }
    uint32_t sb = smem_u32(smem);
    float* colacc = (float*)(smem + 2 * L_STAGE);
    if (COLSUM && tid < 128) colacc[tid] = 0.f;
    const int KbS = (KMAP == 0) ? 4096 : 1024;
    const int nch = (KMAP == 0) ? 48 : 12;
    const int HI  = (KMAP == 0) ? 16 : 4;
    int nit = nch, cbase = 0;
    if (SPLIT == 5) { nit = nch / 2; cbase = blockIdx.z * nit; }
    const char* Abase = ((const char*)A)  + (size_t)(by * 64)  * KbS;
    const char* Bbase = ((const char*)Bw) + (size_t)(bx * 128) * KbS;

    auto load_chunk = [&](int c, int s) {
        int srcA = (c < HI)     ? c : c - HI;
        int srcB = (c < 2 * HI) ? c : c - 2 * HI;
        uint32_t aSt = sb + s * L_STAGE;
        uint32_t bSt = aSt + L_AST;
        int coffA = srcA * 128, coffB = srcB * 128;
        int r = tid >> 3, cc = tid & 7;
        #pragma unroll
        for (int j = 0; j < 2; j++) {
            int rr = r + j * 32;
            cp16(aSt + rr * 144 + cc * 16, Abase + (size_t)rr * KbS + coffA + cc * 16);
        }
        #pragma unroll
        for (int j = 0; j < 4; j++) {
            int rr = r + j * 32;
            cp16(bSt + rr * 144 + cc * 16, Bbase + (size_t)rr * KbS + coffB + cc * 16);
        }
    };

    float d[2][4][4];
    #pragma unroll
    for (int mf = 0; mf < 2; mf++)
        #pragma unroll
        for (int nf = 0; nf < 4; nf++)
            #pragma unroll
            for (int q = 0; q < 4; q++) d[mf][nf][q] = 0.f;

    load_chunk(cbase + 0, 0); CP_COMMIT();
    load_chunk(cbase + 1, 1); CP_COMMIT();

    const int arow_j = ((lane >> 3) & 1) * 8 + (lane & 7);
    const int akb    = (lane >> 4) * 16;
    const int bj     = lane >> 3;
    const int bn_off = (bj >> 1) * 8 + (lane & 7);
    const int bkb    = (bj & 1) * 16;

    for (int c = 0; c < nit; c++) {
        if (c + 1 < nit) { CP_WAIT1(); } else { CP_WAIT0(); }
        __syncthreads();
        uint32_t aSt = sb + (c & 1) * L_STAGE;
        uint32_t bSt = aSt + L_AST;

        #pragma unroll
        for (int ks = 0; ks < 4; ks++) {
            uint32_t a[2][4], b[4][2];
            #pragma unroll
            for (int mf = 0; mf < 2; mf++) {
                int row = wr * 32 + mf * 16 + arow_j;
                ldsm_x4(a[mf], aSt + row * 144 + ks * 32 + akb);
            }
            {
                uint32_t bv[4];
                int row0 = wc * 32 + bn_off;
                ldsm_x4(bv, bSt + row0 * 144 + ks * 32 + bkb);
                b[0][0] = bv[0]; b[0][1] = bv[1]; b[1][0] = bv[2]; b[1][1] = bv[3];
                int row1 = row0 + 16;
                ldsm_x4(bv, bSt + row1 * 144 + ks * 32 + bkb);
                b[2][0] = bv[0]; b[2][1] = bv[1]; b[3][0] = bv[2]; b[3][1] = bv[3];
            }
            #pragma unroll
            for (int mf = 0; mf < 2; mf++)
                #pragma unroll
                for (int nf = 0; nf < 4; nf++)
                    mma_bf16(d[mf][nf], a[mf], b[nf]);
        }
        __syncthreads();
        if (c + 2 < nit) load_chunk(cbase + c + 2, c & 1);
        CP_COMMIT();
    }

    // ---- epilogue ----
    const int g = lane >> 2, tq = lane & 3;
    auto emit = [&](int r, int c, float v0, float v1) {
        if (SPLIT == 5) {
            atomicAdd(&C[(size_t)r * N + c],     v0);
            atomicAdd(&C[(size_t)r * N + c + 1], v1);
            return;
        }
        v0 += bias[c]; v1 += bias[c + 1];
        if (SPLIT == 3) {
            __half2 hh = __floats2half2_rn(v0, v1);
            if (c < 256) {
                g_eh[(size_t)r * DH_ + c]     = v0;
                g_eh[(size_t)r * DH_ + c + 1] = v1;
                *(__half2*)&g_Ah[(size_t)r * DH_ + c] = hh;
            } else {
                int c2 = c - 256;
                g_et[(size_t)r * DH_ + c2]     = v0;
                g_et[(size_t)r * DH_ + c2 + 1] = v1;
                *(__half2*)&g_Bh[(size_t)r * DH_ + c2] = hh;
            }
            return;
        }
        if (LEAKY) { v0 = leaky_f(v0); v1 = leaky_f(v1); }
        if (ADD)   { v0 += Cin[(size_t)r * N + c]; v1 += Cin[(size_t)r * N + c + 1]; }
        if (SPLIT == 4) {
            atomicAdd(&g_s[r], v0 * aux[c] + v1 * aux[c + 1]);
            return;
        }
        C[(size_t)r * N + c]     = v0;
        C[(size_t)r * N + c + 1] = v1;
        if (COLSUM) {
            int cl = c - bx * 128;
            atomicAdd(&colacc[cl], v0);
            atomicAdd(&colacc[cl + 1], v1);
        }
    };
    #pragma unroll
    for (int mf = 0; mf < 2; mf++) {
        #pragma unroll
        for (int nf = 0; nf < 4; nf++) {
            int row = by * 64 + wr * 32 + mf * 16 + g;
            int col = bx * 128 + wc * 32 + nf * 8 + tq * 2;
            emit(row,     col, d[mf][nf][0], d[mf][nf][1]);
            emit(row + 8, col, d[mf][nf][2], d[mf][nf][3]);
        }
    }
    if (COLSUM) {
        __syncthreads();
        if (tid < 128) atomicAdd(&g_mean[bx * 128 + tid], colacc[tid]);
    }
}

// ---------------- NT GEMM (fp16, K=256, BK=64, 2-stage, occ 2): ranking + top-6 --------
#define NT_AST   18432
#define NT_STAGE 55296
#define SMEM_NT  110592

__global__ __launch_bounds__(256, 2)
void gemm_nt_mma() {
    extern __shared__ char smem[];
    const int tid = threadIdx.x;
    const int wid = tid >> 5, lane = tid & 31;
    const int wr = wid >> 2, wc = wid & 3;
    const int bx = blockIdx.x, by = blockIdx.y;
    uint32_t sb = smem_u32(smem);
    const int Kb = DH_ * 2;
    const char* Abase = ((const char*)g_Ah) + (size_t)(by * 128) * Kb;
    const char* Bbase = ((const char*)g_Bh) + (size_t)(bx * 256) * Kb;

    auto load_chunk = [&](int c, int s) {
        uint32_t aSt = sb + s * NT_STAGE;
        uint32_t bSt = aSt + NT_AST;
        int coff = c * 128;
        int r = tid >> 3, cc = tid & 7;
        #pragma unroll
        for (int j = 0; j < 4; j++) {
            int rr = r + j * 32;
            cp16(aSt + rr * 144 + cc * 16, Abase + (size_t)rr * Kb + coff + cc * 16);
        }
        #pragma unroll
        for (int j = 0; j < 8; j++) {
            int rr = r + j * 32;
            cp16(bSt + rr * 144 + cc * 16, Bbase + (size_t)rr * Kb + coff + cc * 16);
        }
    };

    uint32_t d2[4][8][2];
    #pragma unroll
    for (int mf = 0; mf < 4; mf++)
        #pragma unroll
        for (int nf = 0; nf < 8; nf++) { d2[mf][nf][0] = 0u; d2[mf][nf][1] = 0u; }

    load_chunk(0, 0); CP_COMMIT();
    load_chunk(1, 1); CP_COMMIT();

    const int arow_j = ((lane >> 3) & 1) * 8 + (lane & 7);
    const int akb    = (lane >> 4) * 16;
    const int bj     = lane >> 3;
    const int bn_off = (bj >> 1) * 8 + (lane & 7);
    const int bkb    = (bj & 1) * 16;

    for (int c = 0; c < 4; c++) {
        if (c < 3) { CP_WAIT1(); } else { CP_WAIT0(); }
        __syncthreads();
        uint32_t aSt = sb + (c & 1) * NT_STAGE;
        uint32_t bSt = aSt + NT_AST;

        #pragma unroll
        for (int ks = 0; ks < 4; ks++) {
            uint32_t a[4][4], b[8][2];
            #pragma unroll
            for (int mf = 0; mf < 4; mf++) {
                int row = wr * 64 + mf * 16 + arow_j;
                ldsm_x4(a[mf], aSt + row * 144 + ks * 32 + akb);
            }
            #pragma unroll
            for (int nb = 0; nb < 4; nb++) {
                uint32_t bv[4];
                int row = wc * 64 + nb * 16 + bn_off;
                ldsm_x4(bv, bSt + row * 144 + ks * 32 + bkb);
                b[nb*2][0]   = bv[0]; b[nb*2][1]   = bv[1];
                b[nb*2+1][0] = bv[2]; b[nb*2+1][1] = bv[3];
            }
            #pragma unroll
            for (int mf = 0; mf < 4; mf++)
                #pragma unroll
                for (int nf = 0; nf < 8; nf++)
                    mma_f16acc(d2[mf][nf], a[mf], b[nf]);
        }
        __syncthreads();
        if (c + 2 < 4) load_chunk(c + 2, c & 1);
        CP_COMMIT();
    }

    // ---- epilogue in two 64-row phases ----
    float* sE = (float*)smem;
    const int g = lane >> 2, tq = lane & 3;
    #pragma unroll
    for (int ph = 0; ph < 2; ph++) {
        __syncthreads();
        if (wr == ph) {
            #pragma unroll
            for (int mf = 0; mf < 4; mf++) {
                int lr = mf * 16 + g;
                #pragma unroll
                for (int nf = 0; nf < 8; nf++) {
                    int cc = wc * 64 + nf * 8 + tq * 2;
                    __half2 p0 = *(__half2*)&d2[mf][nf][0];
                    __half2 p1 = *(__half2*)&d2[mf][nf][1];
                    sE[lr * 259 + cc]           = __low2float(p0);
                    sE[lr * 259 + cc + 1]       = __high2float(p0);
                    sE[(lr + 8) * 259 + cc]     = __low2float(p1);
                    sE[(lr + 8) * 259 + cc + 1] = __high2float(p1);
                }
            }
        }
        __syncthreads();
        if (tid < 128) {
            int row = tid & 63, ch = tid >> 6;
            float v[6]; int ix[6];
            #pragma unroll
            for (int k = 0; k < 6; k++) { v[k] = NEG_INF; ix[k] = 0; }
            int cb = bx * 256 + ch * 128;
            const float* rp = sE + row * 259 + ch * 128;
            for (int j = 0; j < 128; j++) {
                float val = rp[j] * 0.0625f;
                if (val > v[5]) {
                    v[5] = val; ix[5] = cb + j;
                    #pragma unroll
                    for (int k = 5; k > 0; k--) {
                        if (v[k] > v[k - 1]) {
                            float tv = v[k]; v[k] = v[k - 1]; v[k - 1] = tv;
                            int   ti = ix[k]; ix[k] = ix[k - 1]; ix[k - 1] = ti;
                        }
                    }
                }
            }
            size_t rg = (size_t)by * 128 + ph * 64 + row;
            size_t o = rg * CANDS + bx * 12 + ch * 6;
            #pragma unroll
            for (int k = 0; k < 6; k++) { g_candv[o + k] = v[k]; g_candi[o + k] = ix[k]; }
        }
    }
}

// ---------------- topk v2: shfl-based approx top-8 -> exact rescore -> top-6 -----------
__global__ __launch_bounds__(128)
void topk_msg_kernel() {
    int i = blockIdx.x;
    int t = threadIdx.x;
    int lane = t & 31, wp = t >> 5;
    const float* cv = g_candv + (size_t)i * CANDS;
    const int*   ci = g_candi + (size_t)i * CANDS;

    float lv[3]; int li[3];
    #pragma unroll
    for (int k = 0; k < 3; k++) { lv[k] = NEG_INF; li[k] = 0; }
    #pragma unroll
    for (int j = 0; j < 3; j++) {
        int c = t + j * 128;
        float v = cv[c];
        if (v > lv[2]) {
            lv[2] = v; li[2] = ci[c];
            #pragma unroll
            for (int k = 2; k > 0; k--) {
                if (lv[k] > lv[k - 1]) {
                    float tv = lv[k]; lv[k] = lv[k - 1]; lv[k - 1] = tv;
                    int   tx = li[k]; li[k] = li[k - 1]; li[k - 1] = tx;
                }
            }
        }
    }

    __shared__ float wv[32]; __shared__ int wi[32];
    #pragma unroll
    for (int r = 0; r < 8; r++) {
        float v = lv[0]; int idx = li[0]; int src = lane;
        #pragma unroll
        for (int o = 16; o > 0; o >>= 1) {
            float ov = __shfl_xor_sync(0xffffffffu, v, o);
            int   oi = __shfl_xor_sync(0xffffffffu, idx, o);
            int   os = __shfl_xor_sync(0xffffffffu, src, o);
            if (ov > v || (ov == v && os < src)) { v = ov; idx = oi; src = os; }
        }
        if (lane == 0) { wv[wp * 8 + r] = v; wi[wp * 8 + r] = idx; }
        if (lane == src) {
            lv[0] = lv[1]; li[0] = li[1];
            lv[1] = lv[2]; li[1] = li[2];
            lv[2] = NEG_INF;
        }
    }
    __syncthreads();

    __shared__ int topi[8];
    if (wp == 0) {
        float v = wv[lane]; int idx = wi[lane];
        #pragma unroll
        for (int r = 0; r < 8; r++) {
            float mv = v; int mi = idx; int src = lane;
            #pragma unroll
            for (int o = 16; o > 0; o >>= 1) {
                float ov = __shfl_xor_sync(0xffffffffu, mv, o);
                int   oi = __shfl_xor_sync(0xffffffffu, mi, o);
                int   os = __shfl_xor_sync(0xffffffffu, src, o);
                if (ov > mv || (ov == mv && os < src)) { mv = ov; mi = oi; src = os; }
            }
            if (lane == 0) topi[r] = mi;
            if (lane == src) v = NEG_INF;
        }
    }
    __syncthreads();

    int ti8[8];
    #pragma unroll
    for (int k = 0; k < 8; k++) ti8[k] = topi[k];

    float ehv[2];
    #pragma unroll
    for (int u = 0; u < 2; u++) ehv[u] = g_eh[(size_t)i * DH_ + t + u * 128];

    float nb8[8][2];
    #pragma unroll
    for (int k = 0; k < 8; k++)
        #pragma unroll
        for (int u = 0; u < 2; u++)
            nb8[k][u] = g_et[(size_t)ti8[k] * DH_ + t + u * 128];

    __shared__ float part[4][12];
    __shared__ float tot[12];
    #pragma unroll
    for (int k = 0; k < 8; k++) {
        float s = ehv[0] * nb8[k][0] + ehv[1] * nb8[k][1];
        s = warp_sum(s);
        if (lane == 0) part[wp][k] = s;
    }
    __syncthreads();
    if (t < 8) tot[t] = (part[0][t] + part[1][t] + part[2][t] + part[3][t]) * 0.0625f;
    __syncthreads();

    float val8[8];
    #pragma unroll
    for (int k = 0; k < 8; k++) val8[k] = tot[k];
    int sel[6];
    unsigned used = 0;
    #pragma unroll
    for (int r = 0; r < 6; r++) {
        int best = -1; float bv = NEG_INF;
        #pragma unroll
        for (int k = 0; k < 8; k++) {
            if (!(used >> k & 1) && val8[k] > bv) { bv = val8[k]; best = k; }
        }
        used |= 1u << best;
        sel[r] = best;
    }

    float tv[6];
    float nb[6][2];
    #pragma unroll
    for (int k = 0; k < 6; k++) {
        tv[k] = val8[sel[k]];
        nb[k][0] = nb8[sel[k]][0];
        nb[k][1] = nb8[sel[k]][1];
    }
    float pm = tv[0];
    #pragma unroll
    for (int k = 1; k < 6; k++) pm = fmaxf(pm, tv[k]);
    float pk[6], ps = 0.f;
    #pragma unroll
    for (int k = 0; k < 6; k++) { pk[k] = expf(tv[k] - pm); ps += pk[k]; }
    float pinv = 1.f / ps;
    #pragma unroll
    for (int k = 0; k < 6; k++) pk[k] *= pinv;

    float sN[6], sG[6];
    #pragma unroll
    for (int k = 0; k < 6; k++) { sN[k] = 0.f; sG[k] = 0.f; }
    #pragma unroll
    for (int k = 0; k < 6; k++) {
        #pragma unroll
        for (int u = 0; u < 2; u++) {
            float ehr = pk[k] * nb[k][u] + (1.f - pk[k]) * ehv[u];
            float gt  = tanhf(ehv[u] + ehr);
            sN[k] += nb[k][u];
            sG[k] += gt;
        }
    }

    __syncthreads();
    #pragma unroll
    for (int q = 0; q < 6; q++) {
        float v = warp_sum(sN[q]); if (lane == 0) part[wp][q]     = v;
        float w = warp_sum(sG[q]); if (lane == 0) part[wp][6 + q] = w;
    }
    __syncthreads();
    if (t < 12) tot[t] = part[0][t] + part[1][t] + part[2][t] + part[3][t];
    __syncthreads();

    float kw[6], km = NEG_INF;
    #pragma unroll
    for (int k = 0; k < 6; k++) { kw[k] = tot[k] * tot[6 + k]; km = fmaxf(km, kw[k]); }
    float kp[6], ks = 0.f;
    #pragma unroll
    for (int k = 0; k < 6; k++) { kp[k] = expf(kw[k] - km); ks += kp[k]; }
    float kinv = 1.f / ks;

    #pragma unroll
    for (int u = 0; u < 2; u++) {
        float eN = 0.f;
        #pragma unroll
        for (int k = 0; k < 6; k++) eN += kp[k] * kinv * nb[k][u];
        int dcol = t + u * 128;
        float e = ehv[u];
        float av = e + eN;
        float mv = e * eN;
        __nv_bfloat16 ah = __float2bfloat16(av);
        __nv_bfloat16 al = __float2bfloat16(av - __bfloat162float(ah));
        __nv_bfloat16 mh = __float2bfloat16(mv);
        __nv_bfloat16 ml = __float2bfloat16(mv - __bfloat162float(mh));
        size_t o = (size_t)i * 512 + dcol;
        g_As[o] = ah; g_As[o + 256] = al;
        g_Ms[o] = mh; g_Ms[o + 256] = ml;
    }
}

// ---------------- readout: softmax stats + weighted accumulate ----------------
__global__ __launch_bounds__(1024)
void stat_kernel() {
    int t = threadIdx.x;
    __shared__ float sm[1024];
    float m = NEG_INF;
    for (int i = t; i < NP; i += 1024) m = fmaxf(m, g_s[i]);
    sm[t] = m; __syncthreads();
    for (int o = 512; o > 0; o >>= 1) { if (t < o) sm[t] = fmaxf(sm[t], sm[t + o]); __syncthreads(); }
    float mx = sm[0];
    __syncthreads();
    float e = 0.f;
    for (int i = t; i < NP; i += 1024) e += expf(g_s[i] - mx);
    sm[t] = e; __syncthreads();
    for (int o = 512; o > 0; o >>= 1) { if (t < o) sm[t] += sm[t + o]; __syncthreads(); }
    if (t == 0) { g_stat[0] = mx; g_stat[1] = sm[0]; }
}

__global__ __launch_bounds__(256)
void accum_kernel(const float* __restrict__ emsg, float* __restrict__ eg) {
    int t = threadIdx.x;
    int r0 = blockIdx.x * 256;
    __shared__ float w[256];
    float mx = g_stat[0], inv = 1.f / g_stat[1];
    w[t] = expf(g_s[r0 + t] - mx) * inv;
    __syncthreads();
    float acc = 0.f;
    for (int r = 0; r < 256; r++) acc += w[r] * emsg[(size_t)(r0 + r) * DH_ + t];
    atomicAdd(&eg[t], acc);
}

// ---------------- launcher ----------------
extern "C" void kernel_launch(void* const* d_in, const int* in_sizes, int n_in,
                              void* d_out, int out_size) {
    const float* x_path = (const float*)d_in[0];
    const float* fc1_W  = (const float*)d_in[1];
    const float* fc1_b  = (const float*)d_in[2];
    const float* Wh     = (const float*)d_in[3];
    const float* bh     = (const float*)d_in[4];
    const float* Wt     = (const float*)d_in[5];
    const float* bt     = (const float*)d_in[6];
    const float* W1     = (const float*)d_in[7];
    const float* b1     = (const float*)d_in[8];
    const float* W2     = (const float*)d_in[9];
    const float* b2     = (const float*)d_in[10];
    const float* Ag1    = (const float*)d_in[11];
    const float* bg1    = (const float*)d_in[12];
    const float* Ag2    = (const float*)d_in[13];
    // bg2 unused: softmax over scores is shift-invariant.

    float* out    = (float*)d_out;               // e_msg: 8192 x 256
    float* out_eg = out + (size_t)NP * DH_;      // e_g: 256

    void *px, *peh, *pet, *ph, *pPs, *pXs, *pAs, *pMs, *pEs;
    void *pWfc1, *pWcat, *pW1s, *pW2s, *pAg1s, *pbcat;
    cudaGetSymbolAddress(&px,  g_x);
    cudaGetSymbolAddress(&peh, g_eh);
    cudaGetSymbolAddress(&pet, g_et);
    cudaGetSymbolAddress(&ph,  g_h);
    cudaGetSymbolAddress(&pPs,  g_Ps);
    cudaGetSymbolAddress(&pXs,  g_Xs);
    cudaGetSymbolAddress(&pAs,  g_As);
    cudaGetSymbolAddress(&pMs,  g_Ms);
    cudaGetSymbolAddress(&pEs,  g_Es);
    cudaGetSymbolAddress(&pWfc1, g_Wfc1s);
    cudaGetSymbolAddress(&pWcat, g_Wcat);
    cudaGetSymbolAddress(&pW1s, g_W1s);
    cudaGetSymbolAddress(&pW2s, g_W2s);
    cudaGetSymbolAddress(&pAg1s, g_Ag1s);
    cudaGetSymbolAddress(&pbcat, g_bcat);

    cudaFuncSetAttribute(gemm_nt_mma, cudaFuncAttributeMaxDynamicSharedMemorySize, SMEM_NT);
    cudaFuncSetAttribute(lin_mma<false, false, 5, false, 0>, cudaFuncAttributeMaxDynamicSharedMemorySize, LSMEM_DYN);
    cudaFuncSetAttribute(lin_mma<false, false, 3, false, 1>, cudaFuncAttributeMaxDynamicSharedMemorySize, LSMEM_DYN);
    cudaFuncSetAttribute(lin_mma<true, false, 6, false, 1>,  cudaFuncAttributeMaxDynamicSharedMemorySize, LSMEM_DYN);
    cudaFuncSetAttribute(lin_mma<true, false, 4, false, 1>,  cudaFuncAttributeMaxDynamicSharedMemorySize, LSMEM_DYN);

    // 0: weight splits
    prep_w_kernel<<<2176, 256>>>(fc1_W, Wh, Wt, W1, W2, Ag1);
    // 1: zero g_x + g_s + bcat
    prep_z_kernel<<<2081, 256>>>(bh, bt, out_eg);
    // 2: x_path [h|l] split
    splita_kernel<<<NP * (DIN_/2) / 256, 256>>>(x_path, (__nv_bfloat16*)pPs, DIN_);
    // 3: fc1 K-split x2 -> raw fp32 atomics into g_x  [profiled by ncu -s 5 -c 1]
    lin_mma<false, false, 5, false, 0><<<dim3(2, 128, 2), 256, LSMEM_DYN>>>(
        (const __nv_bfloat16*)pPs, (const __nv_bfloat16*)pWfc1, nullptr, nullptr,
        (float*)px, nullptr, nullptr, nullptr, nullptr, nullptr, nullptr, DH_);
    // 4: fc1 post (bias + leaky + colsum)
    fc1_post_kernel<<<32, 256>>>(fc1_b);
    // 5: mean-mix (+[h|l] split of x)
    mix_split_kernel<<<NP * 128 / 256, 256>>>();
    // 6: merged e_h|e_t (N=512) with routed epilogue
    lin_mma<false, false, 3, false, 1><<<dim3(4, 128), 256, LSMEM_DYN>>>(
        (const __nv_bfloat16*)pXs, (const __nv_bfloat16*)pWcat, (const float*)pbcat,
        nullptr, nullptr, nullptr, nullptr, nullptr, nullptr, nullptr, nullptr, 512);
    // 7: fp16 NT ranking GEMM + fused approx top-6 per chunk
    gemm_nt_mma<<<dim3(32, 64), 256, SMEM_NT>>>();
    // 8: approx top-8 (shfl) -> exact rescore -> exact top-6 -> messages
    topk_msg_kernel<<<NP, 128>>>();
    // 9: W1 || W2 dual GEMM (z=0: leaky(As@W1+b1)->g_eh, z=1: leaky(Ms@W2+b2)->g_et)
    lin_mma<true, false, 6, false, 1><<<dim3(2, 128, 2), 256, LSMEM_DYN>>>(
        (const __nv_bfloat16*)pAs, (const __nv_bfloat16*)pW1s, b1, nullptr,
        (float*)peh, nullptr, nullptr,
        (const __nv_bfloat16*)pMs, (const __nv_bfloat16*)pW2s, b2, (float*)pet, DH_);
    // 10: combine -> out (+Es split)
    combine_kernel<<<NP * 128 / 256, 256>>>(out);
    // 11: readout hidden + fused score
    lin_mma<true, false, 4, false, 1><<<dim3(1, 128), 256, LSMEM_DYN>>>(
        (const __nv_bfloat16*)pEs, (const __nv_bfloat16*)pAg1s, bg1, nullptr,
        (float*)ph, nullptr, Ag2, nullptr, nullptr, nullptr, nullptr, DH_/2);
    // 12-13: softmax stats + gated readout
    stat_kernel<<<1, 1024>>>();
    accum_kernel<<<32, 256>>>(out, out_eg);
}

// round 17
// speedup vs baseline: 1.1179x; 1.1179x over previous
#include <cuda_runtime.h>
#include <cuda_bf16.h>
#include <cuda_fp16.h>
#include <math.h>
#include <stdint.h>

#define NP   8192
#define DIN_ 1024
#define DH_  256
#define CANDS 384
#define NEG_INF (-3.402823466e38f)

// ---------------- scratch (allocation-free: __device__ globals) ----------------
__device__ float g_x [NP*DH_];
__device__ float g_eh[NP*DH_];
__device__ float g_et[NP*DH_];
__device__ __nv_bfloat16 g_Ps [(size_t)NP*2048];    // x_path split [h|l]
__device__ __nv_bfloat16 g_Xs [(size_t)NP*512];     // mixed x split [h|l]
__device__ __half g_Ah [(size_t)NP*DH_];            // e_h fp16 (NT A)
__device__ __half g_Bh [(size_t)NP*DH_];            // e_t fp16 (NT B)
__device__ __nv_bfloat16 g_As [(size_t)NP*512];     // a split [h|l]
__device__ __nv_bfloat16 g_Ms [(size_t)NP*512];     // m split [h|l]
__device__ __nv_bfloat16 g_Es [(size_t)NP*512];     // e_msg split [h|l]
__device__ __nv_bfloat16 g_Wfc1s[(size_t)DH_*2048]; // fc1 W [h|l]
__device__ __nv_bfloat16 g_Wcat [512*512];          // [Wh;Wt] [h|l]
__device__ __nv_bfloat16 g_W1s [DH_*512];
__device__ __nv_bfloat16 g_W2s [DH_*512];
__device__ __nv_bfloat16 g_Ag1s[(DH_/2)*512];
__device__ float g_bcat[512];
__device__ float g_candv[(size_t)NP*CANDS];
__device__ int   g_candi[(size_t)NP*CANDS];
__device__ float g_h [NP*(DH_/2)];
__device__ float g_mean[DH_];
__device__ float g_s[NP];
__device__ float g_stat[2];

__device__ __forceinline__ float leaky_f(float v) { return v > 0.f ? v : 0.01f * v; }

__device__ __forceinline__ float warp_sum(float v) {
    #pragma unroll
    for (int o = 16; o > 0; o >>= 1) v += __shfl_down_sync(0xffffffffu, v, o);
    return v;
}

// ---------------- PTX helpers ----------------
__device__ __forceinline__ uint32_t smem_u32(const void* p) {
    uint32_t a;
    asm("{ .reg .u64 t; cvta.to.shared.u64 t, %1; cvt.u32.u64 %0, t; }" : "=r"(a) : "l"(p));
    return a;
}
__device__ __forceinline__ void cp16(uint32_t dst, const void* src) {
    asm volatile("cp.async.cg.shared.global [%0], [%1], 16;" :: "r"(dst), "l"(src));
}
#define CP_COMMIT()  asm volatile("cp.async.commit_group;" ::: "memory")
#define CP_WAIT1()   asm volatile("cp.async.wait_group 1;" ::: "memory")
#define CP_WAIT0()   asm volatile("cp.async.wait_group 0;" ::: "memory")

__device__ __forceinline__ void ldsm_x4(uint32_t (&r)[4], uint32_t addr) {
    asm volatile("ldmatrix.sync.aligned.m8n8.x4.shared.b16 {%0,%1,%2,%3}, [%4];"
                 : "=r"(r[0]), "=r"(r[1]), "=r"(r[2]), "=r"(r[3]) : "r"(addr));
}
__device__ __forceinline__ void mma_bf16(float (&d)[4], const uint32_t (&a)[4],
                                         const uint32_t* b) {
    asm volatile("mma.sync.aligned.m16n8k16.row.col.f32.bf16.bf16.f32 "
                 "{%0,%1,%2,%3}, {%4,%5,%6,%7}, {%8,%9}, {%0,%1,%2,%3};"
                 : "+f"(d[0]), "+f"(d[1]), "+f"(d[2]), "+f"(d[3])
                 : "r"(a[0]), "r"(a[1]), "r"(a[2]), "r"(a[3]), "r"(b[0]), "r"(b[1]));
}
__device__ __forceinline__ void mma_f16acc(uint32_t (&d)[2], const uint32_t (&a)[4],
                                           const uint32_t* b) {
    asm volatile("mma.sync.aligned.m16n8k16.row.col.f16.f16.f16.f16 "
                 "{%0,%1}, {%2,%3,%4,%5}, {%6,%7}, {%0,%1};"
                 : "+r"(d[0]), "+r"(d[1])
                 : "r"(a[0]), "r"(a[1]), "r"(a[2]), "r"(a[3]), "r"(b[0]), "r"(b[1]));
}

__device__ __forceinline__ void split_pair(float v0, float v1,
                                           __nv_bfloat162& hh, __nv_bfloat162& ll) {
    __nv_bfloat16 h0 = __float2bfloat16(v0), h1 = __float2bfloat16(v1);
    hh.x = h0; hh.y = h1;
    ll.x = __float2bfloat16(v0 - __bfloat162float(h0));
    ll.y = __float2bfloat16(v1 - __bfloat162float(h1));
}

// ---------------- prep 1: weight splits [h|l] ----------------
__device__ __forceinline__ void splitw_body(const float* __restrict__ W,
                                            __nv_bfloat16* __restrict__ out,
                                            int K, int N, int baseRow, int idx) {
    int k = idx / N, n = idx - k * N;
    float v = W[idx];
    __nv_bfloat16 h = __float2bfloat16(v);
    __nv_bfloat16 l = __float2bfloat16(v - __bfloat162float(h));
    size_t o = (size_t)(n + baseRow) * (2 * K);
    out[o + k]     = h;
    out[o + K + k] = l;
}

__global__ void prep_w_kernel(const float* __restrict__ fc1W,
                              const float* __restrict__ Wh, const float* __restrict__ Wt,
                              const float* __restrict__ W1, const float* __restrict__ W2,
                              const float* __restrict__ Ag1) {
    int b = blockIdx.x, t = threadIdx.x;
    if (b < 1024)       splitw_body(fc1W, g_Wfc1s, DIN_, DH_, 0,   b * 256 + t);
    else if (b < 1280)  splitw_body(Wh,   g_Wcat,  DH_, DH_, 0,   (b - 1024) * 256 + t);
    else if (b < 1536)  splitw_body(Wt,   g_Wcat,  DH_, DH_, 256, (b - 1280) * 256 + t);
    else if (b < 1792)  splitw_body(W1,   g_W1s,   DH_, DH_, 0,   (b - 1536) * 256 + t);
    else if (b < 2048)  splitw_body(W2,   g_W2s,   DH_, DH_, 0,   (b - 1792) * 256 + t);
    else                splitw_body(Ag1,  g_Ag1s,  DH_, DH_/2, 0, (b - 2048) * 256 + t);
}

// ---------------- prep 2: zero g_x (for fc1 K-split atomics) + g_s + bcat + mean -------
__global__ void prep_z_kernel(const float* __restrict__ bh, const float* __restrict__ bt,
                              float* __restrict__ eg) {
    int b = blockIdx.x, t = threadIdx.x;
    if (b < 2048) {
        ((float4*)g_x)[b * 256 + t] = make_float4(0.f, 0.f, 0.f, 0.f);
        return;
    }
    int b2 = b - 2048;
    if (b2 < 32) { g_s[b2 * 256 + t] = 0.f; return; }
    g_mean[t] = 0.f;
    eg[t] = 0.f;
    g_bcat[t] = bh[t];
    g_bcat[256 + t] = bt[t];
}

// ---------------- A split: x_path (M x 1024 fp32) -> (M x 2048 bf16) [h|l] ----------------
__global__ __launch_bounds__(256)
void splita_kernel(const float* __restrict__ A, __nv_bfloat16* __restrict__ out, int K) {
    int idx = blockIdx.x * 256 + threadIdx.x;
    int half = K >> 1;
    int row = idx / half, c2 = idx - row * half;
    int col = c2 * 2;
    float2 v = *(const float2*)(A + (size_t)row * K + col);
    __nv_bfloat162 hh, ll;
    split_pair(v.x, v.y, hh, ll);
    size_t o = (size_t)row * (2 * K) + col;
    *(__nv_bfloat162*)&out[o]     = hh;
    *(__nv_bfloat162*)&out[o + K] = ll;
}

// ---------------- fc1 post: bias + leaky + colsum, full-chip grid -------------
__global__ __launch_bounds__(256)
void fc1_post_kernel(const float* __restrict__ bias) {
    int t = threadIdx.x;                 // column
    int r0 = blockIdx.x * 32;            // 256 blocks x 32 rows
    float b = bias[t];
    float acc = 0.f;
    #pragma unroll 4
    for (int r = 0; r < 32; r++) {
        size_t idx = (size_t)(r0 + r) * DH_ + t;
        float v = leaky_f(g_x[idx] + b);
        g_x[idx] = v;
        acc += v;
    }
    atomicAdd(&g_mean[t], acc);
}

// ---------------- mean mix (+fused [h|l] split of x) ----------------
__global__ __launch_bounds__(256)
void mix_split_kernel() {
    int idx = blockIdx.x * 256 + threadIdx.x;
    int row = idx >> 7, c2 = idx & 127;
    int col = c2 * 2;
    float2 v = *(const float2*)(g_x + (size_t)row * DH_ + col);
    float x0 = (v.x + g_mean[col]     * (1.f / (float)NP)) * 0.5f;
    float x1 = (v.y + g_mean[col + 1] * (1.f / (float)NP)) * 0.5f;
    __nv_bfloat162 hh, ll;
    split_pair(x0, x1, hh, ll);
    size_t o = (size_t)row * 512 + col;
    *(__nv_bfloat162*)&g_Xs[o]       = hh;
    *(__nv_bfloat162*)&g_Xs[o + 256] = ll;
}

// ---------------- generic mma.sync linear (BM=64, BN=128, BK=64, 2-stage, occ 3) -------
// SPLIT: 0 none, 1 A-side [h|l] out, 3 ehet routing, 4 fused score,
//        5 raw fp32 atomic out (K-split, blockIdx.z = K-half).
#define L_AST   9216                     // 64*144
#define L_STAGE 27648                    // + 128*144
#define LSMEM_DYN (2 * L_STAGE + 512)

template<bool LEAKY, bool ADD, int SPLIT, bool COLSUM, int KMAP>
__global__ __launch_bounds__(256, 3)
void lin_mma(const __nv_bfloat16* __restrict__ A, const __nv_bfloat16* __restrict__ Bw,
             const float* __restrict__ bias, const float* __restrict__ Cin,
             float* __restrict__ C, __nv_bfloat16* __restrict__ S,
             const float* __restrict__ aux, int N)
{
    extern __shared__ char smem[];
    const int tid = threadIdx.x;
    const int lane = tid & 31, wid = tid >> 5;
    const int wr = wid >> 2, wc = wid & 3;
    const int bx = blockIdx.x, by = blockIdx.y;
    uint32_t sb = smem_u32(smem);
    float* colacc = (float*)(smem + 2 * L_STAGE);
    if (COLSUM && tid < 128) colacc[tid] = 0.f;
    const int KbS = (KMAP == 0) ? 4096 : 1024;
    const int nch = (KMAP == 0) ? 48 : 12;
    const int HI  = (KMAP == 0) ? 16 : 4;
    int nit = nch, cbase = 0;
    if (SPLIT == 5) { nit = nch / 2; cbase = blockIdx.z * nit; }
    const char* Abase = ((const char*)A)  + (size_t)(by * 64)  * KbS;
    const char* Bbase = ((const char*)Bw) + (size_t)(bx * 128) * KbS;

    auto load_chunk = [&](int c, int s) {
        int srcA = (c < HI)     ? c : c - HI;
        int srcB = (c < 2 * HI) ? c : c - 2 * HI;
        uint32_t aSt = sb + s * L_STAGE;
        uint32_t bSt = aSt + L_AST;
        int coffA = srcA * 128, coffB = srcB * 128;
        int r = tid >> 3, cc = tid & 7;
        #pragma unroll
        for (int j = 0; j < 2; j++) {
            int rr = r + j * 32;
            cp16(aSt + rr * 144 + cc * 16, Abase + (size_t)rr * KbS + coffA + cc * 16);
        }
        #pragma unroll
        for (int j = 0; j < 4; j++) {
            int rr = r + j * 32;
            cp16(bSt + rr * 144 + cc * 16, Bbase + (size_t)rr * KbS + coffB + cc * 16);
        }
    };

    float d[2][4][4];
    #pragma unroll
    for (int mf = 0; mf < 2; mf++)
        #pragma unroll
        for (int nf = 0; nf < 4; nf++)
            #pragma unroll
            for (int q = 0; q < 4; q++) d[mf][nf][q] = 0.f;

    load_chunk(cbase + 0, 0); CP_COMMIT();
    load_chunk(cbase + 1, 1); CP_COMMIT();

    const int arow_j = ((lane >> 3) & 1) * 8 + (lane & 7);
    const int akb    = (lane >> 4) * 16;
    const int bj     = lane >> 3;
    const int bn_off = (bj >> 1) * 8 + (lane & 7);
    const int bkb    = (bj & 1) * 16;

    for (int c = 0; c < nit; c++) {
        if (c + 1 < nit) { CP_WAIT1(); } else { CP_WAIT0(); }
        __syncthreads();
        uint32_t aSt = sb + (c & 1) * L_STAGE;
        uint32_t bSt = aSt + L_AST;

        #pragma unroll
        for (int ks = 0; ks < 4; ks++) {
            uint32_t a[2][4], b[4][2];
            #pragma unroll
            for (int mf = 0; mf < 2; mf++) {
                int row = wr * 32 + mf * 16 + arow_j;
                ldsm_x4(a[mf], aSt + row * 144 + ks * 32 + akb);
            }
            {
                uint32_t bv[4];
                int row0 = wc * 32 + bn_off;
                ldsm_x4(bv, bSt + row0 * 144 + ks * 32 + bkb);
                b[0][0] = bv[0]; b[0][1] = bv[1]; b[1][0] = bv[2]; b[1][1] = bv[3];
                int row1 = row0 + 16;
                ldsm_x4(bv, bSt + row1 * 144 + ks * 32 + bkb);
                b[2][0] = bv[0]; b[2][1] = bv[1]; b[3][0] = bv[2]; b[3][1] = bv[3];
            }
            #pragma unroll
            for (int mf = 0; mf < 2; mf++)
                #pragma unroll
                for (int nf = 0; nf < 4; nf++)
                    mma_bf16(d[mf][nf], a[mf], b[nf]);
        }
        __syncthreads();
        if (c + 2 < nit) load_chunk(cbase + c + 2, c & 1);
        CP_COMMIT();
    }

    // ---- epilogue ----
    const int g = lane >> 2, tq = lane & 3;
    auto emit = [&](int r, int c, float v0, float v1) {
        if (SPLIT == 5) {
            atomicAdd(&C[(size_t)r * N + c],     v0);
            atomicAdd(&C[(size_t)r * N + c + 1], v1);
            return;
        }
        v0 += bias[c]; v1 += bias[c + 1];
        if (SPLIT == 3) {
            __half2 hh = __floats2half2_rn(v0, v1);
            if (c < 256) {
                g_eh[(size_t)r * DH_ + c]     = v0;
                g_eh[(size_t)r * DH_ + c + 1] = v1;
                *(__half2*)&g_Ah[(size_t)r * DH_ + c] = hh;
            } else {
                int c2 = c - 256;
                g_et[(size_t)r * DH_ + c2]     = v0;
                g_et[(size_t)r * DH_ + c2 + 1] = v1;
                *(__half2*)&g_Bh[(size_t)r * DH_ + c2] = hh;
            }
            return;
        }
        if (LEAKY) { v0 = leaky_f(v0); v1 = leaky_f(v1); }
        if (ADD)   { v0 += Cin[(size_t)r * N + c]; v1 += Cin[(size_t)r * N + c + 1]; }
        if (SPLIT == 4) {
            atomicAdd(&g_s[r], v0 * aux[c] + v1 * aux[c + 1]);
            return;
        }
        C[(size_t)r * N + c]     = v0;
        C[(size_t)r * N + c + 1] = v1;
        if (COLSUM) {
            int cl = c - bx * 128;
            atomicAdd(&colacc[cl], v0);
            atomicAdd(&colacc[cl + 1], v1);
        }
        if (SPLIT == 1) {
            __nv_bfloat162 hh, ll;
            split_pair(v0, v1, hh, ll);
            size_t o = (size_t)r * 512 + c;
            *(__nv_bfloat162*)&S[o]       = hh;
            *(__nv_bfloat162*)&S[o + 256] = ll;
        }
    };
    #pragma unroll
    for (int mf = 0; mf < 2; mf++) {
        #pragma unroll
        for (int nf = 0; nf < 4; nf++) {
            int row = by * 64 + wr * 32 + mf * 16 + g;
            int col = bx * 128 + wc * 32 + nf * 8 + tq * 2;
            emit(row,     col, d[mf][nf][0], d[mf][nf][1]);
            emit(row + 8, col, d[mf][nf][2], d[mf][nf][3]);
        }
    }
    if (COLSUM) {
        __syncthreads();
        if (tid < 128) atomicAdd(&g_mean[bx * 128 + tid], colacc[tid]);
    }
}

// ---------------- NT GEMM (fp16, K=256, BK=64, 2-stage, occ 2): ranking + top-6 --------
#define NT_AST   18432
#define NT_STAGE 55296
#define SMEM_NT  110592

__global__ __launch_bounds__(256, 2)
void gemm_nt_mma() {
    extern __shared__ char smem[];
    const int tid = threadIdx.x;
    const int wid = tid >> 5, lane = tid & 31;
    const int wr = wid >> 2, wc = wid & 3;
    const int bx = blockIdx.x, by = blockIdx.y;
    uint32_t sb = smem_u32(smem);
    const int Kb = DH_ * 2;
    const char* Abase = ((const char*)g_Ah) + (size_t)(by * 128) * Kb;
    const char* Bbase = ((const char*)g_Bh) + (size_t)(bx * 256) * Kb;

    auto load_chunk = [&](int c, int s) {
        uint32_t aSt = sb + s * NT_STAGE;
        uint32_t bSt = aSt + NT_AST;
        int coff = c * 128;
        int r = tid >> 3, cc = tid & 7;
        #pragma unroll
        for (int j = 0; j < 4; j++) {
            int rr = r + j * 32;
            cp16(aSt + rr * 144 + cc * 16, Abase + (size_t)rr * Kb + coff + cc * 16);
        }
        #pragma unroll
        for (int j = 0; j < 8; j++) {
            int rr = r + j * 32;
            cp16(bSt + rr * 144 + cc * 16, Bbase + (size_t)rr * Kb + coff + cc * 16);
        }
    };

    uint32_t d2[4][8][2];
    #pragma unroll
    for (int mf = 0; mf < 4; mf++)
        #pragma unroll
        for (int nf = 0; nf < 8; nf++) { d2[mf][nf][0] = 0u; d2[mf][nf][1] = 0u; }

    load_chunk(0, 0); CP_COMMIT();
    load_chunk(1, 1); CP_COMMIT();

    const int arow_j = ((lane >> 3) & 1) * 8 + (lane & 7);
    const int akb    = (lane >> 4) * 16;
    const int bj     = lane >> 3;
    const int bn_off = (bj >> 1) * 8 + (lane & 7);
    const int bkb    = (bj & 1) * 16;

    for (int c = 0; c < 4; c++) {
        if (c < 3) { CP_WAIT1(); } else { CP_WAIT0(); }
        __syncthreads();
        uint32_t aSt = sb + (c & 1) * NT_STAGE;
        uint32_t bSt = aSt + NT_AST;

        #pragma unroll
        for (int ks = 0; ks < 4; ks++) {
            uint32_t a[4][4], b[8][2];
            #pragma unroll
            for (int mf = 0; mf < 4; mf++) {
                int row = wr * 64 + mf * 16 + arow_j;
                ldsm_x4(a[mf], aSt + row * 144 + ks * 32 + akb);
            }
            #pragma unroll
            for (int nb = 0; nb < 4; nb++) {
                uint32_t bv[4];
                int row = wc * 64 + nb * 16 + bn_off;
                ldsm_x4(bv, bSt + row * 144 + ks * 32 + bkb);
                b[nb*2][0]   = bv[0]; b[nb*2][1]   = bv[1];
                b[nb*2+1][0] = bv[2]; b[nb*2+1][1] = bv[3];
            }
            #pragma unroll
            for (int mf = 0; mf < 4; mf++)
                #pragma unroll
                for (int nf = 0; nf < 8; nf++)
                    mma_f16acc(d2[mf][nf], a[mf], b[nf]);
        }
        __syncthreads();
        if (c + 2 < 4) load_chunk(c + 2, c & 1);
        CP_COMMIT();
    }

    // ---- epilogue in two 64-row phases ----
    float* sE = (float*)smem;
    const int g = lane >> 2, tq = lane & 3;
    #pragma unroll
    for (int ph = 0; ph < 2; ph++) {
        __syncthreads();
        if (wr == ph) {
            #pragma unroll
            for (int mf = 0; mf < 4; mf++) {
                int lr = mf * 16 + g;
                #pragma unroll
                for (int nf = 0; nf < 8; nf++) {
                    int cc = wc * 64 + nf * 8 + tq * 2;
                    __half2 p0 = *(__half2*)&d2[mf][nf][0];
                    __half2 p1 = *(__half2*)&d2[mf][nf][1];
                    sE[lr * 259 + cc]           = __low2float(p0);
                    sE[lr * 259 + cc + 1]       = __high2float(p0);
                    sE[(lr + 8) * 259 + cc]     = __low2float(p1);
                    sE[(lr + 8) * 259 + cc + 1] = __high2float(p1);
                }
            }
        }
        __syncthreads();
        if (tid < 128) {
            int row = tid & 63, ch = tid >> 6;
            float v[6]; int ix[6];
            #pragma unroll
            for (int k = 0; k < 6; k++) { v[k] = NEG_INF; ix[k] = 0; }
            int cb = bx * 256 + ch * 128;
            const float* rp = sE + row * 259 + ch * 128;
            for (int j = 0; j < 128; j++) {
                float val = rp[j] * 0.0625f;
                if (val > v[5]) {
                    v[5] = val; ix[5] = cb + j;
                    #pragma unroll
                    for (int k = 5; k > 0; k--) {
                        if (v[k] > v[k - 1]) {
                            float tv = v[k]; v[k] = v[k - 1]; v[k - 1] = tv;
                            int   ti = ix[k]; ix[k] = ix[k - 1]; ix[k - 1] = ti;
                        }
                    }
                }
            }
            size_t rg = (size_t)by * 128 + ph * 64 + row;
            size_t o = rg * CANDS + bx * 12 + ch * 6;
            #pragma unroll
            for (int k = 0; k < 6; k++) { g_candv[o + k] = v[k]; g_candi[o + k] = ix[k]; }
        }
    }
}

// ---------------- topk v2: shfl-based approx top-8 -> exact rescore -> top-6 -----------
__global__ __launch_bounds__(128)
void topk_msg_kernel() {
    int i = blockIdx.x;
    int t = threadIdx.x;
    int lane = t & 31, wp = t >> 5;
    const float* cv = g_candv + (size_t)i * CANDS;
    const int*   ci = g_candi + (size_t)i * CANDS;

    float lv[3]; int li[3];
    #pragma unroll
    for (int k = 0; k < 3; k++) { lv[k] = NEG_INF; li[k] = 0; }
    #pragma unroll
    for (int j = 0; j < 3; j++) {
        int c = t + j * 128;
        float v = cv[c];
        if (v > lv[2]) {
            lv[2] = v; li[2] = ci[c];
            #pragma unroll
            for (int k = 2; k > 0; k--) {
                if (lv[k] > lv[k - 1]) {
                    float tv = lv[k]; lv[k] = lv[k - 1]; lv[k - 1] = tv;
                    int   tx = li[k]; li[k] = li[k - 1]; li[k - 1] = tx;
                }
            }
        }
    }

    __shared__ float wv[32]; __shared__ int wi[32];
    #pragma unroll
    for (int r = 0; r < 8; r++) {
        float v = lv[0]; int idx = li[0]; int src = lane;
        #pragma unroll
        for (int o = 16; o > 0; o >>= 1) {
            float ov = __shfl_xor_sync(0xffffffffu, v, o);
            int   oi = __shfl_xor_sync(0xffffffffu, idx, o);
            int   os = __shfl_xor_sync(0xffffffffu, src, o);
            if (ov > v || (ov == v && os < src)) { v = ov; idx = oi; src = os; }
        }
        if (lane == 0) { wv[wp * 8 + r] = v; wi[wp * 8 + r] = idx; }
        if (lane == src) {
            lv[0] = lv[1]; li[0] = li[1];
            lv[1] = lv[2]; li[1] = li[2];
            lv[2] = NEG_INF;
        }
    }
    __syncthreads();

    __shared__ int topi[8];
    if (wp == 0) {
        float v = wv[lane]; int idx = wi[lane];
        #pragma unroll
        for (int r = 0; r < 8; r++) {
            float mv = v; int mi = idx; int src = lane;
            #pragma unroll
            for (int o = 16; o > 0; o >>= 1) {
                float ov = __shfl_xor_sync(0xffffffffu, mv, o);
                int   oi = __shfl_xor_sync(0xffffffffu, mi, o);
                int   os = __shfl_xor_sync(0xffffffffu, src, o);
                if (ov > mv || (ov == mv && os < src)) { mv = ov; mi = oi; src = os; }
            }
            if (lane == 0) topi[r] = mi;
            if (lane == src) v = NEG_INF;
        }
    }
    __syncthreads();

    int ti8[8];
    #pragma unroll
    for (int k = 0; k < 8; k++) ti8[k] = topi[k];

    float ehv[2];
    #pragma unroll
    for (int u = 0; u < 2; u++) ehv[u] = g_eh[(size_t)i * DH_ + t + u * 128];

    float nb8[8][2];
    #pragma unroll
    for (int k = 0; k < 8; k++)
        #pragma unroll
        for (int u = 0; u < 2; u++)
            nb8[k][u] = g_et[(size_t)ti8[k] * DH_ + t + u * 128];

    __shared__ float part[4][12];
    __shared__ float tot[12];
    #pragma unroll
    for (int k = 0; k < 8; k++) {
        float s = ehv[0] * nb8[k][0] + ehv[1] * nb8[k][1];
        s = warp_sum(s);
        if (lane == 0) part[wp][k] = s;
    }
    __syncthreads();
    if (t < 8) tot[t] = (part[0][t] + part[1][t] + part[2][t] + part[3][t]) * 0.0625f;
    __syncthreads();

    float val8[8];
    #pragma unroll
    for (int k = 0; k < 8; k++) val8[k] = tot[k];
    int sel[6];
    unsigned used = 0;
    #pragma unroll
    for (int r = 0; r < 6; r++) {
        int best = -1; float bv = NEG_INF;
        #pragma unroll
        for (int k = 0; k < 8; k++) {
            if (!(used >> k & 1) && val8[k] > bv) { bv = val8[k]; best = k; }
        }
        used |= 1u << best;
        sel[r] = best;
    }

    float tv[6];
    float nb[6][2];
    #pragma unroll
    for (int k = 0; k < 6; k++) {
        tv[k] = val8[sel[k]];
        nb[k][0] = nb8[sel[k]][0];
        nb[k][1] = nb8[sel[k]][1];
    }
    float pm = tv[0];
    #pragma unroll
    for (int k = 1; k < 6; k++) pm = fmaxf(pm, tv[k]);
    float pk[6], ps = 0.f;
    #pragma unroll
    for (int k = 0; k < 6; k++) { pk[k] = expf(tv[k] - pm); ps += pk[k]; }
    float pinv = 1.f / ps;
    #pragma unroll
    for (int k = 0; k < 6; k++) pk[k] *= pinv;

    float sN[6], sG[6];
    #pragma unroll
    for (int k = 0; k < 6; k++) { sN[k] = 0.f; sG[k] = 0.f; }
    #pragma unroll
    for (int k = 0; k < 6; k++) {
        #pragma unroll
        for (int u = 0; u < 2; u++) {
            float ehr = pk[k] * nb[k][u] + (1.f - pk[k]) * ehv[u];
            float gt  = tanhf(ehv[u] + ehr);
            sN[k] += nb[k][u];
            sG[k] += gt;
        }
    }

    __syncthreads();
    #pragma unroll
    for (int q = 0; q < 6; q++) {
        float v = warp_sum(sN[q]); if (lane == 0) part[wp][q]     = v;
        float w = warp_sum(sG[q]); if (lane == 0) part[wp][6 + q] = w;
    }
    __syncthreads();
    if (t < 12) tot[t] = part[0][t] + part[1][t] + part[2][t] + part[3][t];
    __syncthreads();

    float kw[6], km = NEG_INF;
    #pragma unroll
    for (int k = 0; k < 6; k++) { kw[k] = tot[k] * tot[6 + k]; km = fmaxf(km, kw[k]); }
    float kp[6], ks = 0.f;
    #pragma unroll
    for (int k = 0; k < 6; k++) { kp[k] = expf(kw[k] - km); ks += kp[k]; }
    float kinv = 1.f / ks;

    #pragma unroll
    for (int u = 0; u < 2; u++) {
        float eN = 0.f;
        #pragma unroll
        for (int k = 0; k < 6; k++) eN += kp[k] * kinv * nb[k][u];
        int dcol = t + u * 128;
        float e = ehv[u];
        float av = e + eN;
        float mv = e * eN;
        __nv_bfloat16 ah = __float2bfloat16(av);
        __nv_bfloat16 al = __float2bfloat16(av - __bfloat162float(ah));
        __nv_bfloat16 mh = __float2bfloat16(mv);
        __nv_bfloat16 ml = __float2bfloat16(mv - __bfloat162float(mh));
        size_t o = (size_t)i * 512 + dcol;
        g_As[o] = ah; g_As[o + 256] = al;
        g_Ms[o] = mh; g_Ms[o + 256] = ml;
    }
}

// ---------------- readout: softmax stats + weighted accumulate ----------------
__global__ __launch_bounds__(1024)
void stat_kernel() {
    int t = threadIdx.x;
    __shared__ float sm[1024];
    float m = NEG_INF;
    for (int i = t; i < NP; i += 1024) m = fmaxf(m, g_s[i]);
    sm[t] = m; __syncthreads();
    for (int o = 512; o > 0; o >>= 1) { if (t < o) sm[t] = fmaxf(sm[t], sm[t + o]); __syncthreads(); }
    float mx = sm[0];
    __syncthreads();
    float e = 0.f;
    for (int i = t; i < NP; i += 1024) e += expf(g_s[i] - mx);
    sm[t] = e; __syncthreads();
    for (int o = 512; o > 0; o >>= 1) { if (t < o) sm[t] += sm[t + o]; __syncthreads(); }
    if (t == 0) { g_stat[0] = mx; g_stat[1] = sm[0]; }
}

__global__ __launch_bounds__(256)
void accum_kernel(const float* __restrict__ emsg, float* __restrict__ eg) {
    int t = threadIdx.x;
    int r0 = blockIdx.x * 256;
    __shared__ float w[256];
    float mx = g_stat[0], inv = 1.f / g_stat[1];
    w[t] = expf(g_s[r0 + t] - mx) * inv;
    __syncthreads();
    float acc = 0.f;
    for (int r = 0; r < 256; r++) acc += w[r] * emsg[(size_t)(r0 + r) * DH_ + t];
    atomicAdd(&eg[t], acc);
}

// ---------------- launcher ----------------
extern "C" void kernel_launch(void* const* d_in, const int* in_sizes, int n_in,
                              void* d_out, int out_size) {
    const float* x_path = (const float*)d_in[0];
    const float* fc1_W  = (const float*)d_in[1];
    const float* fc1_b  = (const float*)d_in[2];
    const float* Wh     = (const float*)d_in[3];
    const float* bh     = (const float*)d_in[4];
    const float* Wt     = (const float*)d_in[5];
    const float* bt     = (const float*)d_in[6];
    const float* W1     = (const float*)d_in[7];
    const float* b1     = (const float*)d_in[8];
    const float* W2     = (const float*)d_in[9];
    const float* b2     = (const float*)d_in[10];
    const float* Ag1    = (const float*)d_in[11];
    const float* bg1    = (const float*)d_in[12];
    const float* Ag2    = (const float*)d_in[13];
    // bg2 unused: softmax over scores is shift-invariant.

    float* out    = (float*)d_out;               // e_msg: 8192 x 256
    float* out_eg = out + (size_t)NP * DH_;      // e_g: 256

    void *px, *ph, *pPs, *pXs, *pAs, *pMs, *pEs;
    void *pWfc1, *pWcat, *pW1s, *pW2s, *pAg1s, *pbcat;
    cudaGetSymbolAddress(&px,  g_x);
    cudaGetSymbolAddress(&ph,  g_h);
    cudaGetSymbolAddress(&pPs,  g_Ps);
    cudaGetSymbolAddress(&pXs,  g_Xs);
    cudaGetSymbolAddress(&pAs,  g_As);
    cudaGetSymbolAddress(&pMs,  g_Ms);
    cudaGetSymbolAddress(&pEs,  g_Es);
    cudaGetSymbolAddress(&pWfc1, g_Wfc1s);
    cudaGetSymbolAddress(&pWcat, g_Wcat);
    cudaGetSymbolAddress(&pW1s, g_W1s);
    cudaGetSymbolAddress(&pW2s, g_W2s);
    cudaGetSymbolAddress(&pAg1s, g_Ag1s);
    cudaGetSymbolAddress(&pbcat, g_bcat);

    cudaFuncSetAttribute(gemm_nt_mma, cudaFuncAttributeMaxDynamicSharedMemorySize, SMEM_NT);
    cudaFuncSetAttribute(lin_mma<false, false, 5, false, 0>, cudaFuncAttributeMaxDynamicSharedMemorySize, LSMEM_DYN);
    cudaFuncSetAttribute(lin_mma<true, false, 0, false, 1>,  cudaFuncAttributeMaxDynamicSharedMemorySize, LSMEM_DYN);
    cudaFuncSetAttribute(lin_mma<false, false, 3, false, 1>, cudaFuncAttributeMaxDynamicSharedMemorySize, LSMEM_DYN);
    cudaFuncSetAttribute(lin_mma<true, true, 1, false, 1>,   cudaFuncAttributeMaxDynamicSharedMemorySize, LSMEM_DYN);
    cudaFuncSetAttribute(lin_mma<true, false, 4, false, 1>,  cudaFuncAttributeMaxDynamicSharedMemorySize, LSMEM_DYN);

    // 0: weight splits
    prep_w_kernel<<<2176, 256>>>(fc1_W, Wh, Wt, W1, W2, Ag1);
    // 1: zero g_x + g_s + bcat + mean
    prep_z_kernel<<<2081, 256>>>(bh, bt, out_eg);
    // 2: x_path [h|l] split
    splita_kernel<<<NP * (DIN_/2) / 256, 256>>>(x_path, (__nv_bfloat16*)pPs, DIN_);
    // 3: fc1 K-split x2 -> raw fp32 atomics into g_x  [profiled by ncu -s 5 -c 1]
    lin_mma<false, false, 5, false, 0><<<dim3(2, 128, 2), 256, LSMEM_DYN>>>(
        (const __nv_bfloat16*)pPs, (const __nv_bfloat16*)pWfc1, nullptr, nullptr,
        (float*)px, nullptr, nullptr, DH_);
    // 4: fc1 post (bias + leaky + colsum), full-chip grid
    fc1_post_kernel<<<256, 256>>>(fc1_b);
    // 5: mean-mix (+[h|l] split of x)
    mix_split_kernel<<<NP * 128 / 256, 256>>>();
    // 6: merged e_h|e_t (N=512) with routed epilogue
    lin_mma<false, false, 3, false, 1><<<dim3(4, 128), 256, LSMEM_DYN>>>(
        (const __nv_bfloat16*)pXs, (const __nv_bfloat16*)pWcat, (const float*)pbcat,
        nullptr, nullptr, nullptr, nullptr, 512);
    // 7: fp16 NT ranking GEMM + fused approx top-6 per chunk
    gemm_nt_mma<<<dim3(32, 64), 256, SMEM_NT>>>();
    // 8: approx top-8 (shfl) -> exact rescore -> exact top-6 -> messages
    topk_msg_kernel<<<NP, 128>>>();
    // 9-10: e_msg = leaky(a@W1+b1) + leaky(m@W2+b2) -> out (+[h|l] split for Ag1)
    lin_mma<true, false, 0, false, 1><<<dim3(2, 128), 256, LSMEM_DYN>>>(
        (const __nv_bfloat16*)pAs, (const __nv_bfloat16*)pW1s, b1, nullptr,
        out, nullptr, nullptr, DH_);
    lin_mma<true, true, 1, false, 1><<<dim3(2, 128), 256, LSMEM_DYN>>>(
        (const __nv_bfloat16*)pMs, (const __nv_bfloat16*)pW2s, b2, out,
        out, (__nv_bfloat16*)pEs, nullptr, DH_);
    // 11: readout hidden + fused score
    lin_mma<true, false, 4, false, 1><<<dim3(1, 128), 256, LSMEM_DYN>>>(
        (const __nv_bfloat16*)pEs, (const __nv_bfloat16*)pAg1s, bg1, nullptr,
        (float*)ph, nullptr, Ag2, DH_/2);
    // 12-13: softmax stats + gated readout
    stat_kernel<<<1, 1024>>>();
    accum_kernel<<<32, 256>>>(out, out_eg);
}